// round 10
// baseline (speedup 1.0000x reference)
#include <cuda_runtime.h>
#include <cuda_fp16.h>

// WormnetCell: liquid time-constant cell, semi-implicit ODE, 6 unfolds.
// BATCH=8192 rows, U=128 units, IN=32 sensory inputs.
//
// R9: R8's bf16x2-tanh structure, precision-rebalanced:
//  - unfolds 0..2: tanh.approx.bf16x2 (1 XU op / 2 sigmoids); args exact fp32
//    -> cvt.rn.bf16x2.f32 (alu-class), bf16->f32 unpack = pure bit ops (ALU),
//    accumulation exact fp32 via fma.rn.f32x2
//  - unfolds 3..5: full fp32 tanh (damps bf16 noise by J^3: measured 1.95e-3
//    with 1 fp32 final -> predicted ~2e-4 with 3)

#define UDIM 128
#define INDIM 32
#define RPB 8
#define NUNFOLDS 6
#define NBF 3            // number of bf16 unfolds (0..NBF-1)

typedef unsigned long long u64;

// i-paired recurrent params, indexed [pair*UDIM + j]:
//   g_PA = {a_even, nb_even, a_odd, nb_odd}   (a = 0.5*sigma, nb = -0.5*sigma*mu)
//   g_PW = {we_even, w_even, we_odd, w_odd}   (we = 0.5*W*erev, w = 0.5*W)
__device__ float4 g_PA[(UDIM / 2) * UDIM];
__device__ float4 g_PW[(UDIM / 2) * UDIM];
// Sensory params fp32: {a, nb, we, w}
__device__ float4 g_Psen[INDIM * UDIM];
// Per-unit constant halves (sum of we / w over all 160 inputs)
__device__ float  g_Cnum[UDIM];
__device__ float  g_Cden[UDIM];

__device__ __forceinline__ float tanh_fast(float x) {
    float y; asm("tanh.approx.f32 %0, %1;" : "=f"(y) : "f"(x)); return y;
}
// one XU op, two bf16 tanh evals
__device__ __forceinline__ unsigned tanh2_bf16(unsigned x) {
    unsigned y; asm("tanh.approx.bf16x2 %0, %1;" : "=r"(y) : "r"(x)); return y;
}
// pack two exact f32 -> bf16x2 (F2FP, alu-class). d.hi = cvt(hi), d.lo = cvt(lo)
__device__ __forceinline__ unsigned cvt_bf16x2(float hi, float lo) {
    unsigned d; asm("cvt.rn.bf16x2.f32 %0, %1, %2;" : "=r"(d) : "f"(hi), "f"(lo)); return d;
}
__device__ __forceinline__ u64 ffma2(u64 a, u64 b, u64 c) {
    u64 d; asm("fma.rn.f32x2 %0, %1, %2, %3;" : "=l"(d) : "l"(a), "l"(b), "l"(c)); return d;
}
__device__ __forceinline__ u64 pack2(float lo, float hi) {
    u64 r; asm("mov.b64 %0, {%1, %2};" : "=l"(r) : "f"(lo), "f"(hi)); return r;
}
__device__ __forceinline__ float2 unpack2(u64 v) {
    float2 f; asm("mov.b64 {%0, %1}, %2;" : "=f"(f.x), "=f"(f.y) : "l"(v)); return f;
}
// bf16x2 -> f32x2 via pure bit ops (ALU pipe): lane-lo = h.lo<<16, lane-hi = h.hi&mask
__device__ __forceinline__ u64 bf16x2_to_f32x2(unsigned h) {
    u64 r;
    asm("mov.b64 %0, {%1, %2};" : "=l"(r) : "r"(h << 16), "r"(h & 0xFFFF0000u));
    return r;
}

// One block per unit-column j (128 blocks x 160 threads).
__global__ void prep_kernel(const float* __restrict__ mu, const float* __restrict__ sig,
                            const float* __restrict__ W, const float* __restrict__ erev,
                            const float* __restrict__ smu, const float* __restrict__ ssig,
                            const float* __restrict__ sW, const float* __restrict__ serev)
{
    __shared__ float sn[UDIM + INDIM];
    __shared__ float sd[UDIM + INDIM];
    const int j = blockIdx.x;
    const int i = threadIdx.x;

    float we, w;
    if (i < UDIM) {
        int idx = i * UDIM + j;
        float a  = 0.5f * sig[idx];
        float nb = -a * mu[idx];
        w  = 0.5f * W[idx];
        we = w * erev[idx];
        int pair = i >> 1, half = i & 1;
        reinterpret_cast<float2*>(&g_PA[pair * UDIM + j])[half] = make_float2(a, nb);
        reinterpret_cast<float2*>(&g_PW[pair * UDIM + j])[half] = make_float2(we, w);
    } else {
        int idx = (i - UDIM) * UDIM + j;
        float a = 0.5f * ssig[idx];
        w  = 0.5f * sW[idx];
        we = w * serev[idx];
        g_Psen[idx] = make_float4(a, -a * smu[idx], we, w);
    }
    sn[i] = we;
    sd[i] = w;
    __syncthreads();

    if (i == 0) {
        float cn = 0.f, cd = 0.f;
        #pragma unroll 8
        for (int k = 0; k < UDIM + INDIM; k++) { cn += sn[k]; cd += sd[k]; }
        g_Cnum[j] = cn;
        g_Cden[j] = cd;
    }
}

__global__ void __launch_bounds__(UDIM, 7)
worm_kernel(const float* __restrict__ inputs, const float* __restrict__ state,
            const float* __restrict__ vleak, const float* __restrict__ gleak,
            const float* __restrict__ cm,
            const float* __restrict__ in_w, const float* __restrict__ in_b,
            const float* __restrict__ out_w, const float* __restrict__ out_b,
            float* __restrict__ out_y, float* __restrict__ out_v)
{
    __shared__ __align__(16) float vT[2][UDIM * RPB];   // double-buffered state [i][r]
    __shared__ __align__(16) float sBn[UDIM * RPB];     // base num per (j, r)
    __shared__ __align__(16) float sBd[UDIM * RPB];     // base den per (j, r)
    __shared__ float xT[INDIM * RPB];

    const int j = threadIdx.x;                          // unit index 0..127
    const long long row0 = (long long)blockIdx.x * RPB;

    // ---- state -> vT[0] ----
    #pragma unroll
    for (int r = 0; r < RPB; r++)
        vT[0][j * RPB + r] = state[(row0 + r) * UDIM + j];

    // ---- inputs with affine map ----
    #pragma unroll
    for (int k = 0; k < (INDIM * RPB) / UDIM; k++) {
        int idx = k * UDIM + j;
        int r = idx / INDIM, i = idx % INDIM;
        xT[i * RPB + r] = fmaf(inputs[(row0 + r) * INDIM + i], __ldg(&in_w[i]), __ldg(&in_b[i]));
    }
    __syncthreads();

    // ---- sensory contribution (fp32, once) + constant halves -> smem ----
    {
        float bnum[RPB], bden[RPB];
        float c0 = g_Cnum[j], d0 = g_Cden[j];
        #pragma unroll
        for (int r = 0; r < RPB; r++) { bnum[r] = c0; bden[r] = d0; }

        #pragma unroll 4
        for (int i = 0; i < INDIM; i++) {
            float4 p = __ldg(&g_Psen[i * UDIM + j]);
            const float4* xp = reinterpret_cast<const float4*>(&xT[i * RPB]);
            float4 x0 = xp[0], x1 = xp[1];
            float xv[RPB] = {x0.x, x0.y, x0.z, x0.w, x1.x, x1.y, x1.z, x1.w};
            #pragma unroll
            for (int r = 0; r < RPB; r++) {
                float th = tanh_fast(fmaf(p.x, xv[r], p.y));
                bnum[r] = fmaf(p.z, th, bnum[r]);
                bden[r] = fmaf(p.w, th, bden[r]);
            }
        }
        #pragma unroll
        for (int r = 0; r < RPB; r++) {
            sBn[j * RPB + r] = bnum[r];
            sBd[j * RPB + r] = bden[r];
        }
    }

    const float cmj = cm[j];
    const float glj = gleak[j];
    const float gvj = glj * vleak[j];
    const float cgj = cmj + glj;

    // ================= unfolds 0..NBF-1: bf16x2 tanh path =================
    #pragma unroll 1
    for (int t = 0; t < NBF; t++) {
        const int cur = t & 1, nxt = cur ^ 1;
        const float* __restrict__ vc = vT[cur];

        // f32x2 accumulators: lanes = (even-i partial, odd-i partial)
        u64 num2[RPB], den2[RPB];
        #pragma unroll
        for (int r = 0; r < RPB; r++) {
            num2[r] = pack2(sBn[j * RPB + r], 0.0f);
            den2[r] = pack2(sBd[j * RPB + r], 0.0f);
        }

        #pragma unroll 1
        for (int pi = 0; pi < UDIM / 2; pi++) {
            const float4 pa = __ldg(&g_PA[pi * UDIM + j]);  // {a0, nb0, a1, nb1}
            const float4 pw = __ldg(&g_PW[pi * UDIM + j]);  // {we0, w0, we1, w1}
            const u64 we2 = pack2(pw.x, pw.z);
            const u64 w2  = pack2(pw.y, pw.w);

            const float4* vpa = reinterpret_cast<const float4*>(&vc[(2 * pi)     * RPB]);
            const float4* vpb = reinterpret_cast<const float4*>(&vc[(2 * pi + 1) * RPB]);
            float4 a0 = vpa[0], a1 = vpa[1];    // v_even rows 0..7 (broadcast LDS.128)
            float4 b0 = vpb[0], b1 = vpb[1];    // v_odd  rows 0..7
            float va[RPB] = {a0.x, a0.y, a0.z, a0.w, a1.x, a1.y, a1.z, a1.w};
            float vb[RPB] = {b0.x, b0.y, b0.z, b0.w, b1.x, b1.y, b1.z, b1.w};

            #pragma unroll
            for (int r = 0; r < RPB; r++) {
                float arg0 = fmaf(pa.x, va[r], pa.y);   // even-i arg (exact fp32)
                float arg1 = fmaf(pa.z, vb[r], pa.w);   // odd-i arg
                unsigned h = cvt_bf16x2(arg1, arg0);    // hi=arg1, lo=arg0
                h = tanh2_bf16(h);                      // 1 XU op, 2 tanh
                u64 th2 = bf16x2_to_f32x2(h);           // ALU-only widen
                num2[r] = ffma2(we2, th2, num2[r]);
                den2[r] = ffma2(w2,  th2, den2[r]);
            }
        }

        // old v (own slots) before buffer swap
        float vold[RPB];
        {
            const float4* vo = reinterpret_cast<const float4*>(&vc[j * RPB]);
            float4 a = vo[0], b = vo[1];
            vold[0]=a.x; vold[1]=a.y; vold[2]=a.z; vold[3]=a.w;
            vold[4]=b.x; vold[5]=b.y; vold[6]=b.z; vold[7]=b.w;
        }

        float vn[RPB];
        #pragma unroll
        for (int r = 0; r < RPB; r++) {
            float2 nf = unpack2(num2[r]);
            float2 df = unpack2(den2[r]);
            float num = nf.x + nf.y, den = df.x + df.y;
            vn[r] = __fdividef(fmaf(cmj, vold[r], gvj + num), cgj + den);
        }

        float4* vw = reinterpret_cast<float4*>(&vT[nxt][j * RPB]);
        vw[0] = make_float4(vn[0], vn[1], vn[2], vn[3]);
        vw[1] = make_float4(vn[4], vn[5], vn[6], vn[7]);
        __syncthreads();
    }

    // ================= unfolds NBF..NUNFOLDS-2: full fp32 =================
    #pragma unroll 1
    for (int t = NBF; t < NUNFOLDS - 1; t++) {
        const int cur = t & 1, nxt = cur ^ 1;
        const float* __restrict__ vc = vT[cur];

        float num[RPB], den[RPB];
        #pragma unroll
        for (int r = 0; r < RPB; r++) {
            num[r] = sBn[j * RPB + r];
            den[r] = sBd[j * RPB + r];
        }

        #pragma unroll 1
        for (int pi = 0; pi < UDIM / 2; pi++) {
            const float4 pa = __ldg(&g_PA[pi * UDIM + j]);
            const float4 pw = __ldg(&g_PW[pi * UDIM + j]);

            const float4* vpa = reinterpret_cast<const float4*>(&vc[(2 * pi)     * RPB]);
            const float4* vpb = reinterpret_cast<const float4*>(&vc[(2 * pi + 1) * RPB]);
            float4 a0 = vpa[0], a1 = vpa[1];
            float4 b0 = vpb[0], b1 = vpb[1];
            float va[RPB] = {a0.x, a0.y, a0.z, a0.w, a1.x, a1.y, a1.z, a1.w};
            float vb[RPB] = {b0.x, b0.y, b0.z, b0.w, b1.x, b1.y, b1.z, b1.w};

            #pragma unroll
            for (int r = 0; r < RPB; r++) {
                float th0 = tanh_fast(fmaf(pa.x, va[r], pa.y));
                float th1 = tanh_fast(fmaf(pa.z, vb[r], pa.w));
                num[r] = fmaf(pw.x, th0, num[r]);
                den[r] = fmaf(pw.y, th0, den[r]);
                num[r] = fmaf(pw.z, th1, num[r]);
                den[r] = fmaf(pw.w, th1, den[r]);
            }
        }

        float vold[RPB];
        {
            const float4* vo = reinterpret_cast<const float4*>(&vc[j * RPB]);
            float4 a = vo[0], b = vo[1];
            vold[0]=a.x; vold[1]=a.y; vold[2]=a.z; vold[3]=a.w;
            vold[4]=b.x; vold[5]=b.y; vold[6]=b.z; vold[7]=b.w;
        }

        float vn[RPB];
        #pragma unroll
        for (int r = 0; r < RPB; r++)
            vn[r] = __fdividef(fmaf(cmj, vold[r], gvj + num[r]), cgj + den[r]);

        float4* vw = reinterpret_cast<float4*>(&vT[nxt][j * RPB]);
        vw[0] = make_float4(vn[0], vn[1], vn[2], vn[3]);
        vw[1] = make_float4(vn[4], vn[5], vn[6], vn[7]);
        __syncthreads();
    }

    // ================= final unfold (fp32) fused with output =================
    {
        const float* __restrict__ vc = vT[(NUNFOLDS - 1) & 1];

        float num[RPB], den[RPB];
        #pragma unroll
        for (int r = 0; r < RPB; r++) {
            num[r] = sBn[j * RPB + r];
            den[r] = sBd[j * RPB + r];
        }

        #pragma unroll 1
        for (int pi = 0; pi < UDIM / 2; pi++) {
            const float4 pa = __ldg(&g_PA[pi * UDIM + j]);
            const float4 pw = __ldg(&g_PW[pi * UDIM + j]);

            const float4* vpa = reinterpret_cast<const float4*>(&vc[(2 * pi)     * RPB]);
            const float4* vpb = reinterpret_cast<const float4*>(&vc[(2 * pi + 1) * RPB]);
            float4 a0 = vpa[0], a1 = vpa[1];
            float4 b0 = vpb[0], b1 = vpb[1];
            float va[RPB] = {a0.x, a0.y, a0.z, a0.w, a1.x, a1.y, a1.z, a1.w};
            float vb[RPB] = {b0.x, b0.y, b0.z, b0.w, b1.x, b1.y, b1.z, b1.w};

            #pragma unroll
            for (int r = 0; r < RPB; r++) {
                float th0 = tanh_fast(fmaf(pa.x, va[r], pa.y));
                float th1 = tanh_fast(fmaf(pa.z, vb[r], pa.w));
                num[r] = fmaf(pw.x, th0, num[r]);
                den[r] = fmaf(pw.y, th0, den[r]);
                num[r] = fmaf(pw.z, th1, num[r]);
                den[r] = fmaf(pw.w, th1, den[r]);
            }
        }

        float vold[RPB];
        {
            const float4* vo = reinterpret_cast<const float4*>(&vc[j * RPB]);
            float4 a = vo[0], b = vo[1];
            vold[0]=a.x; vold[1]=a.y; vold[2]=a.z; vold[3]=a.w;
            vold[4]=b.x; vold[5]=b.y; vold[6]=b.z; vold[7]=b.w;
        }

        float ow = 0.f, ob = 0.f;
        if (out_y && j == 0) { ow = __ldg(&out_w[0]); ob = __ldg(&out_b[0]); }

        #pragma unroll
        for (int r = 0; r < RPB; r++) {
            float vn = __fdividef(fmaf(cmj, vold[r], gvj + num[r]), cgj + den[r]);
            if (out_v) out_v[(row0 + r) * UDIM + j] = vn;
            if (out_y && j == 0) out_y[row0 + r] = fmaf(vn, ow, ob);
        }
    }
}

extern "C" void kernel_launch(void* const* d_in, const int* in_sizes, int n_in,
                              void* d_out, int out_size)
{
    const float* inputs = (const float*)d_in[0];
    const float* state  = (const float*)d_in[1];
    const float* smu    = (const float*)d_in[2];
    const float* ssig   = (const float*)d_in[3];
    const float* sW     = (const float*)d_in[4];
    const float* serev  = (const float*)d_in[5];
    const float* mu     = (const float*)d_in[6];
    const float* sig    = (const float*)d_in[7];
    const float* W      = (const float*)d_in[8];
    const float* erev   = (const float*)d_in[9];
    const float* vleak  = (const float*)d_in[10];
    const float* gleak  = (const float*)d_in[11];
    const float* cm     = (const float*)d_in[12];
    const float* in_w   = (const float*)d_in[13];
    const float* in_b   = (const float*)d_in[14];
    const float* out_w  = (const float*)d_in[15];
    const float* out_b  = (const float*)d_in[16];

    const int batch = in_sizes[1] / UDIM;   // 8192

    float* out   = (float*)d_out;
    float* out_y = nullptr;
    float* out_v = nullptr;
    if (out_size == batch + batch * UDIM) {       // (outputs, v) concatenated
        out_y = out;
        out_v = out + batch;
    } else if (out_size == batch * UDIM) {        // v only
        out_v = out;
    } else {                                      // outputs only
        out_y = out;
    }

    prep_kernel<<<UDIM, UDIM + INDIM>>>(mu, sig, W, erev, smu, ssig, sW, serev);
    worm_kernel<<<batch / RPB, UDIM>>>(inputs, state, vleak, gleak, cm,
                                       in_w, in_b, out_w, out_b, out_y, out_v);
}

// round 12
// speedup vs baseline: 1.0944x; 1.0944x over previous
#include <cuda_runtime.h>
#include <cuda_fp16.h>
#include <cmath>

// WormnetCell: liquid time-constant cell, semi-implicit ODE, 6 unfolds.
// BATCH=8192 rows, U=128 units, IN=32 sensory inputs.
//
// R10: XU (MUFU.TANH, rt 8) is 100% saturated; packed tanh (f16x2/bf16x2)
// proved rate-neutral on sm_103a. So offload a static fraction of sigmoids
// to the half-idle FMA/ALU pipes:
//  - source units i < ISPLIT(20): tanh via odd degree-19 polynomial x*P(x^2)
//    on [-4,4] (clamped); coefficients = Chebyshev interpolation of tanh
//    computed IN DOUBLE ON THE HOST per call, passed as kernel params
//    (constant bank -> uniform regs, no register pressure)
//  - source units i >= 20: MUFU.TANH path, identical to R7
//  - everything else identical to R7 (fp32, lb(128,7), double-buffered vT)

#define UDIM 128
#define INDIM 32
#define RPB 8
#define NUNFOLDS 6
#define ISPLIT 20          // units evaluated via FMA-pipe polynomial
#define NQ 10              // poly coeffs (degree 19 odd)
#define PCLAMP 4.0f

struct PolyCo { float q[NQ]; };

// Packed per-synapse params: {a = 0.5*sigma, nb = -0.5*sigma*mu, we = 0.5*W*erev, w = 0.5*W}
__device__ float4 g_Prec[UDIM * UDIM];
__device__ float4 g_Psen[INDIM * UDIM];
// Per-unit constant halves (sum of we / w over all 160 inputs)
__device__ float  g_Cnum[UDIM];
__device__ float  g_Cden[UDIM];

__device__ __forceinline__ float tanh_fast(float x) {
    float y; asm("tanh.approx.f32 %0, %1;" : "=f"(y) : "f"(x)); return y;
}

// One block per unit-column j (128 blocks x 160 threads).
__global__ void prep_kernel(const float* __restrict__ mu, const float* __restrict__ sig,
                            const float* __restrict__ W, const float* __restrict__ erev,
                            const float* __restrict__ smu, const float* __restrict__ ssig,
                            const float* __restrict__ sW, const float* __restrict__ serev)
{
    __shared__ float sn[UDIM + INDIM];
    __shared__ float sd[UDIM + INDIM];
    const int j = blockIdx.x;
    const int i = threadIdx.x;

    float we, w;
    if (i < UDIM) {
        int idx = i * UDIM + j;
        float a = 0.5f * sig[idx];
        w  = 0.5f * W[idx];
        we = w * erev[idx];
        g_Prec[idx] = make_float4(a, -a * mu[idx], we, w);
    } else {
        int idx = (i - UDIM) * UDIM + j;
        float a = 0.5f * ssig[idx];
        w  = 0.5f * sW[idx];
        we = w * serev[idx];
        g_Psen[idx] = make_float4(a, -a * smu[idx], we, w);
    }
    sn[i] = we;
    sd[i] = w;
    __syncthreads();

    if (i == 0) {
        float cn = 0.f, cd = 0.f;
        #pragma unroll 8
        for (int k = 0; k < UDIM + INDIM; k++) { cn += sn[k]; cd += sd[k]; }
        g_Cnum[j] = cn;
        g_Cden[j] = cd;
    }
}

__global__ void __launch_bounds__(UDIM, 7)
worm_kernel(const float* __restrict__ inputs, const float* __restrict__ state,
            const float* __restrict__ vleak, const float* __restrict__ gleak,
            const float* __restrict__ cm,
            const float* __restrict__ in_w, const float* __restrict__ in_b,
            const float* __restrict__ out_w, const float* __restrict__ out_b,
            float* __restrict__ out_y, float* __restrict__ out_v,
            const PolyCo pc)
{
    __shared__ __align__(16) float vT[2][UDIM * RPB];   // double-buffered state
    __shared__ __align__(16) float sBn[UDIM * RPB];     // base num per (j, r)
    __shared__ __align__(16) float sBd[UDIM * RPB];     // base den per (j, r)
    __shared__ float xT[INDIM * RPB];

    const int j = threadIdx.x;                          // unit index 0..127
    const long long row0 = (long long)blockIdx.x * RPB;

    // ---- state -> vT[0] ----
    #pragma unroll
    for (int r = 0; r < RPB; r++)
        vT[0][j * RPB + r] = state[(row0 + r) * UDIM + j];

    // ---- inputs with affine map ----
    #pragma unroll
    for (int k = 0; k < (INDIM * RPB) / UDIM; k++) {
        int idx = k * UDIM + j;
        int r = idx / INDIM, i = idx % INDIM;
        xT[i * RPB + r] = fmaf(inputs[(row0 + r) * INDIM + i], __ldg(&in_w[i]), __ldg(&in_b[i]));
    }
    __syncthreads();

    // ---- sensory contribution (fixed across unfolds) + constant halves -> smem ----
    {
        float bnum[RPB], bden[RPB];
        float c0 = g_Cnum[j], d0 = g_Cden[j];
        #pragma unroll
        for (int r = 0; r < RPB; r++) { bnum[r] = c0; bden[r] = d0; }

        #pragma unroll 4
        for (int i = 0; i < INDIM; i++) {
            float4 p = __ldg(&g_Psen[i * UDIM + j]);
            const float4* xp = reinterpret_cast<const float4*>(&xT[i * RPB]);
            float4 x0 = xp[0], x1 = xp[1];
            float xv[RPB] = {x0.x, x0.y, x0.z, x0.w, x1.x, x1.y, x1.z, x1.w};
            #pragma unroll
            for (int r = 0; r < RPB; r++) {
                float th = tanh_fast(fmaf(p.x, xv[r], p.y));
                bnum[r] = fmaf(p.z, th, bnum[r]);
                bden[r] = fmaf(p.w, th, bden[r]);
            }
        }
        #pragma unroll
        for (int r = 0; r < RPB; r++) {
            sBn[j * RPB + r] = bnum[r];
            sBd[j * RPB + r] = bden[r];
        }
    }

    const float cmj = cm[j];
    const float glj = gleak[j];
    const float gvj = glj * vleak[j];
    const float cgj = cmj + glj;

    #pragma unroll 1
    for (int t = 0; t < NUNFOLDS; t++) {
        const int cur = t & 1, nxt = cur ^ 1;
        const float* __restrict__ vc = vT[cur];

        float num[RPB], den[RPB];
        {
            const float4* bn = reinterpret_cast<const float4*>(&sBn[j * RPB]);
            const float4* bd = reinterpret_cast<const float4*>(&sBd[j * RPB]);
            float4 n0 = bn[0], n1 = bn[1], d0 = bd[0], d1 = bd[1];
            num[0]=n0.x; num[1]=n0.y; num[2]=n0.z; num[3]=n0.w;
            num[4]=n1.x; num[5]=n1.y; num[6]=n1.z; num[7]=n1.w;
            den[0]=d0.x; den[1]=d0.y; den[2]=d0.z; den[3]=d0.w;
            den[4]=d1.x; den[5]=d1.y; den[6]=d1.z; den[7]=d1.w;
        }

        // ===== units 0..ISPLIT-1: polynomial tanh on the FMA/ALU pipes =====
        #pragma unroll 1
        for (int i = 0; i < ISPLIT; i++) {
            const float4 p = __ldg(&g_Prec[i * UDIM + j]);
            const float4* vp = reinterpret_cast<const float4*>(&vc[i * RPB]);
            float4 v0 = vp[0], v1 = vp[1];              // broadcast LDS.128
            float vv[RPB] = {v0.x, v0.y, v0.z, v0.w, v1.x, v1.y, v1.z, v1.w};
            #pragma unroll
            for (int r = 0; r < RPB; r++) {
                float arg = fmaf(p.x, vv[r], p.y);
                float tcl = fminf(fmaxf(arg, -PCLAMP), PCLAMP);
                float y   = tcl * tcl;
                float pp  = pc.q[NQ - 1];
                #pragma unroll
                for (int c = NQ - 2; c >= 0; c--)
                    pp = fmaf(pp, y, pc.q[c]);
                float th = pp * tcl;
                num[r] = fmaf(p.z, th, num[r]);
                den[r] = fmaf(p.w, th, den[r]);
            }
        }

        // ===== units ISPLIT..127: MUFU.TANH path (R7, 2-deep prefetch) =====
        float4 P0 = __ldg(&g_Prec[ISPLIT * UDIM + j]);
        float4 P1 = __ldg(&g_Prec[(ISPLIT + 1) * UDIM + j]);

        #pragma unroll 1
        for (int i = ISPLIT; i < UDIM; i += 2) {
            const int n0i = (i + 2 < UDIM) ? (i + 2) : ISPLIT;  // wrap: harmless reload
            float4 N0 = __ldg(&g_Prec[n0i * UDIM + j]);
            float4 N1 = __ldg(&g_Prec[(n0i + 1) * UDIM + j]);

            #pragma unroll
            for (int k = 0; k < 2; k++) {
                const float4 p = (k == 0) ? P0 : P1;
                const float4* vp = reinterpret_cast<const float4*>(&vc[(i + k) * RPB]);
                float4 v0 = vp[0], v1 = vp[1];          // broadcast LDS.128
                float vv[RPB] = {v0.x, v0.y, v0.z, v0.w, v1.x, v1.y, v1.z, v1.w};
                #pragma unroll
                for (int r = 0; r < RPB; r++) {
                    float th = tanh_fast(fmaf(p.x, vv[r], p.y));
                    num[r] = fmaf(p.z, th, num[r]);
                    den[r] = fmaf(p.w, th, den[r]);
                }
            }
            P0 = N0; P1 = N1;
        }

        // old v (own slots) from current buffer
        float vold[RPB];
        {
            const float4* vo = reinterpret_cast<const float4*>(&vc[j * RPB]);
            float4 a = vo[0], b = vo[1];
            vold[0]=a.x; vold[1]=a.y; vold[2]=a.z; vold[3]=a.w;
            vold[4]=b.x; vold[5]=b.y; vold[6]=b.z; vold[7]=b.w;
        }

        float vn[RPB];
        #pragma unroll
        for (int r = 0; r < RPB; r++)
            vn[r] = __fdividef(fmaf(cmj, vold[r], gvj + num[r]), cgj + den[r]);

        float4* vw = reinterpret_cast<float4*>(&vT[nxt][j * RPB]);
        vw[0] = make_float4(vn[0], vn[1], vn[2], vn[3]);
        vw[1] = make_float4(vn[4], vn[5], vn[6], vn[7]);

        __syncthreads();
    }

    // ---- outputs: final state sits in vT[NUNFOLDS & 1] ----
    const float* vf = vT[NUNFOLDS & 1];
    if (out_v) {
        #pragma unroll
        for (int r = 0; r < RPB; r++)
            out_v[(row0 + r) * UDIM + j] = vf[j * RPB + r];
    }
    if (out_y && j == 0) {
        float ow = __ldg(&out_w[0]), ob = __ldg(&out_b[0]);
        #pragma unroll
        for (int r = 0; r < RPB; r++)
            out_y[row0 + r] = fmaf(vf[r], ow, ob);      // j == 0 -> slots 0..7
    }
}

// Host: degree-19 odd Chebyshev interpolation of tanh on [-PCLAMP, PCLAMP],
// converted to monomial form th(x) ~= x * P(x^2), P of degree 9.
// Deterministic (pure function of compile-time constants).
static PolyCo make_poly_host()
{
    const int NN = 64, KD = 19;
    const double B = (double)PCLAMP;
    const double PI = 3.14159265358979323846;

    double a[KD + 1];
    for (int k = 0; k <= KD; k++) a[k] = 0.0;
    for (int c = 0; c < NN; c++) {
        double th = PI * (c + 0.5) / NN;
        double f  = std::tanh(B * std::cos(th));
        for (int k = 1; k <= KD; k += 2)
            a[k] += (2.0 / NN) * f * std::cos(k * th);
    }

    // accumulate monomial coefficients m[j] of sum_k a[k]*T_k(u), odd k
    double Tp[KD + 1], Tc[KD + 1], Tn[KD + 1], m[KD + 1];
    for (int jj = 0; jj <= KD; jj++) { Tp[jj] = 0; Tc[jj] = 0; m[jj] = 0; }
    Tp[0] = 1.0;                 // T0 = 1
    Tc[1] = 1.0;                 // T1 = u
    m[1] += a[1];                // a1 * T1
    for (int k = 2; k <= KD; k++) {
        for (int jj = 0; jj <= KD; jj++) Tn[jj] = -Tp[jj];
        for (int jj = 0; jj <  KD; jj++) Tn[jj + 1] += 2.0 * Tc[jj];
        if (k & 1)
            for (int jj = 1; jj <= KD; jj += 2) m[jj] += a[k] * Tn[jj];
        for (int jj = 0; jj <= KD; jj++) { Tp[jj] = Tc[jj]; Tc[jj] = Tn[jj]; }
    }

    // q[t] = m[2t+1] / B^(2t+1)
    PolyCo pc;
    double Bp = B;
    for (int t = 0; t < NQ; t++) {
        pc.q[t] = (float)(m[2 * t + 1] / Bp);
        Bp *= B * B;
    }
    return pc;
}

extern "C" void kernel_launch(void* const* d_in, const int* in_sizes, int n_in,
                              void* d_out, int out_size)
{
    const float* inputs = (const float*)d_in[0];
    const float* state  = (const float*)d_in[1];
    const float* smu    = (const float*)d_in[2];
    const float* ssig   = (const float*)d_in[3];
    const float* sW     = (const float*)d_in[4];
    const float* serev  = (const float*)d_in[5];
    const float* mu     = (const float*)d_in[6];
    const float* sig    = (const float*)d_in[7];
    const float* W      = (const float*)d_in[8];
    const float* erev   = (const float*)d_in[9];
    const float* vleak  = (const float*)d_in[10];
    const float* gleak  = (const float*)d_in[11];
    const float* cm     = (const float*)d_in[12];
    const float* in_w   = (const float*)d_in[13];
    const float* in_b   = (const float*)d_in[14];
    const float* out_w  = (const float*)d_in[15];
    const float* out_b  = (const float*)d_in[16];

    const int batch = in_sizes[1] / UDIM;   // 8192

    float* out   = (float*)d_out;
    float* out_y = nullptr;
    float* out_v = nullptr;
    if (out_size == batch + batch * UDIM) {       // (outputs, v) concatenated
        out_y = out;
        out_v = out + batch;
    } else if (out_size == batch * UDIM) {        // v only
        out_v = out;
    } else {                                      // outputs only
        out_y = out;
    }

    const PolyCo pc = make_poly_host();           // deterministic, pure host math

    prep_kernel<<<UDIM, UDIM + INDIM>>>(mu, sig, W, erev, smu, ssig, sW, serev);
    worm_kernel<<<batch / RPB, UDIM>>>(inputs, state, vleak, gleak, cm,
                                       in_w, in_b, out_w, out_b, out_y, out_v, pc);
}

// round 13
// speedup vs baseline: 1.2228x; 1.1174x over previous
#include <cuda_runtime.h>
#include <cuda_fp16.h>

// WormnetCell: liquid time-constant cell, semi-implicit ODE, 6 unfolds.
// BATCH=8192 rows, U=128 units, IN=32 sensory inputs.
//
// R11: XU (MUFU.TANH) saturated; R10 showed any offload costing >4 fma-ops
// per sigmoid just makes FMA the binder. Offload 28/128 source units to a
// shared-memory tanh TABLE (nearest entry, 3072 x f32 on [-6,6], h=1/256):
//   arg FFMA (1/h folded into params) -> clamp (2 FMNMX, alu) ->
//   +2^23 magic FADD (round-to-nearest in mantissa) -> mask (alu) ->
//   LDS.32 -> 2 FFMA accum.   4 fma / 3 alu / 1 LDS / 0 XU per sigmoid.
// Units 28..127 keep the R7 MUFU.TANH path. Everything else = R7.

#define UDIM 128
#define INDIM 32
#define RPB 8
#define NUNFOLDS 6

#define TSPLIT 28              // units evaluated via smem table
#define TABN 3072              // table entries
#define TAB_INVH 256.0f        // 1/h  (h = 12/3072 = 1/256)
#define TAB_OFF 1536.0f        // 6/h  (arg -6 maps to index 0)
#define FMAGIC 8388608.0f      // 2^23

// Packed per-synapse params:
//  i <  TSPLIT: {a/h, nb/h + TAB_OFF, we, w}   (table-unit form)
//  i >= TSPLIT: {a,   nb,             we, w}   (a = 0.5*sigma, nb = -0.5*sigma*mu)
//  we = 0.5*W*erev, w = 0.5*W
__device__ float4 g_Prec[UDIM * UDIM];
__device__ float4 g_Psen[INDIM * UDIM];
// Per-unit constant halves (sum of we / w over all 160 inputs)
__device__ float  g_Cnum[UDIM];
__device__ float  g_Cden[UDIM];

__device__ __forceinline__ float tanh_fast(float x) {
    float y; asm("tanh.approx.f32 %0, %1;" : "=f"(y) : "f"(x)); return y;
}

// One block per unit-column j (128 blocks x 160 threads).
__global__ void prep_kernel(const float* __restrict__ mu, const float* __restrict__ sig,
                            const float* __restrict__ W, const float* __restrict__ erev,
                            const float* __restrict__ smu, const float* __restrict__ ssig,
                            const float* __restrict__ sW, const float* __restrict__ serev)
{
    __shared__ float sn[UDIM + INDIM];
    __shared__ float sd[UDIM + INDIM];
    const int j = blockIdx.x;
    const int i = threadIdx.x;

    float we, w;
    if (i < UDIM) {
        int idx = i * UDIM + j;
        float a  = 0.5f * sig[idx];
        float nb = -a * mu[idx];
        w  = 0.5f * W[idx];
        we = w * erev[idx];
        if (i < TSPLIT)
            g_Prec[idx] = make_float4(a * TAB_INVH, nb * TAB_INVH + TAB_OFF, we, w);
        else
            g_Prec[idx] = make_float4(a, nb, we, w);
    } else {
        int idx = (i - UDIM) * UDIM + j;
        float a = 0.5f * ssig[idx];
        w  = 0.5f * sW[idx];
        we = w * serev[idx];
        g_Psen[idx] = make_float4(a, -a * smu[idx], we, w);
    }
    sn[i] = we;
    sd[i] = w;
    __syncthreads();

    if (i == 0) {
        float cn = 0.f, cd = 0.f;
        #pragma unroll 8
        for (int k = 0; k < UDIM + INDIM; k++) { cn += sn[k]; cd += sd[k]; }
        g_Cnum[j] = cn;
        g_Cden[j] = cd;
    }
}

__global__ void __launch_bounds__(UDIM, 7)
worm_kernel(const float* __restrict__ inputs, const float* __restrict__ state,
            const float* __restrict__ vleak, const float* __restrict__ gleak,
            const float* __restrict__ cm,
            const float* __restrict__ in_w, const float* __restrict__ in_b,
            const float* __restrict__ out_w, const float* __restrict__ out_b,
            float* __restrict__ out_y, float* __restrict__ out_v)
{
    __shared__ __align__(16) float vT[2][UDIM * RPB];   // double-buffered state
    __shared__ __align__(16) float sBn[UDIM * RPB];     // base num per (j, r)
    __shared__ __align__(16) float sBd[UDIM * RPB];     // base den per (j, r)
    __shared__ float xT[INDIM * RPB];
    __shared__ float tab[TABN];                          // tanh table on [-6, 6]

    const int j = threadIdx.x;                           // unit index 0..127
    const long long row0 = (long long)blockIdx.x * RPB;

    // ---- fill tanh table (24 entries/thread) ----
    #pragma unroll
    for (int k = j; k < TABN; k += UDIM)
        tab[k] = tanh_fast((float)k * (1.0f / TAB_INVH) - 6.0f);

    // ---- state -> vT[0] ----
    #pragma unroll
    for (int r = 0; r < RPB; r++)
        vT[0][j * RPB + r] = state[(row0 + r) * UDIM + j];

    // ---- inputs with affine map ----
    #pragma unroll
    for (int k = 0; k < (INDIM * RPB) / UDIM; k++) {
        int idx = k * UDIM + j;
        int r = idx / INDIM, i = idx % INDIM;
        xT[i * RPB + r] = fmaf(inputs[(row0 + r) * INDIM + i], __ldg(&in_w[i]), __ldg(&in_b[i]));
    }
    __syncthreads();

    // ---- sensory contribution (fixed across unfolds) + constant halves -> smem ----
    {
        float bnum[RPB], bden[RPB];
        float c0 = g_Cnum[j], d0 = g_Cden[j];
        #pragma unroll
        for (int r = 0; r < RPB; r++) { bnum[r] = c0; bden[r] = d0; }

        #pragma unroll 4
        for (int i = 0; i < INDIM; i++) {
            float4 p = __ldg(&g_Psen[i * UDIM + j]);
            const float4* xp = reinterpret_cast<const float4*>(&xT[i * RPB]);
            float4 x0 = xp[0], x1 = xp[1];
            float xv[RPB] = {x0.x, x0.y, x0.z, x0.w, x1.x, x1.y, x1.z, x1.w};
            #pragma unroll
            for (int r = 0; r < RPB; r++) {
                float th = tanh_fast(fmaf(p.x, xv[r], p.y));
                bnum[r] = fmaf(p.z, th, bnum[r]);
                bden[r] = fmaf(p.w, th, bden[r]);
            }
        }
        #pragma unroll
        for (int r = 0; r < RPB; r++) {
            sBn[j * RPB + r] = bnum[r];
            sBd[j * RPB + r] = bden[r];
        }
    }

    const float cmj = cm[j];
    const float glj = gleak[j];
    const float gvj = glj * vleak[j];
    const float cgj = cmj + glj;

    #pragma unroll 1
    for (int t = 0; t < NUNFOLDS; t++) {
        const int cur = t & 1, nxt = cur ^ 1;
        const float* __restrict__ vc = vT[cur];

        float num[RPB], den[RPB];
        {
            const float4* bn = reinterpret_cast<const float4*>(&sBn[j * RPB]);
            const float4* bd = reinterpret_cast<const float4*>(&sBd[j * RPB]);
            float4 n0 = bn[0], n1 = bn[1], d0 = bd[0], d1 = bd[1];
            num[0]=n0.x; num[1]=n0.y; num[2]=n0.z; num[3]=n0.w;
            num[4]=n1.x; num[5]=n1.y; num[6]=n1.z; num[7]=n1.w;
            den[0]=d0.x; den[1]=d0.y; den[2]=d0.z; den[3]=d0.w;
            den[4]=d1.x; den[5]=d1.y; den[6]=d1.z; den[7]=d1.w;
        }

        // ===== units 0..TSPLIT-1: smem tanh table (no XU) =====
        #pragma unroll 2
        for (int i = 0; i < TSPLIT; i++) {
            const float4 p = __ldg(&g_Prec[i * UDIM + j]);
            const float4* vp = reinterpret_cast<const float4*>(&vc[i * RPB]);
            float4 v0 = vp[0], v1 = vp[1];               // broadcast LDS.128
            float vv[RPB] = {v0.x, v0.y, v0.z, v0.w, v1.x, v1.y, v1.z, v1.w};
            #pragma unroll
            for (int r = 0; r < RPB; r++) {
                float u  = fmaf(p.x, vv[r], p.y);        // arg in table units
                u = fminf(fmaxf(u, 0.0f), (float)(TABN - 1));
                float mg = u + FMAGIC;                   // round-to-nearest in mantissa
                int idx  = __float_as_int(mg) & 0x0FFF;  // TABN-1 = 0xBFF fits
                float th = tab[idx];
                num[r] = fmaf(p.z, th, num[r]);
                den[r] = fmaf(p.w, th, den[r]);
            }
        }

        // ===== units TSPLIT..127: MUFU.TANH path (2-deep prefetch) =====
        float4 P0 = __ldg(&g_Prec[TSPLIT * UDIM + j]);
        float4 P1 = __ldg(&g_Prec[(TSPLIT + 1) * UDIM + j]);

        #pragma unroll 1
        for (int i = TSPLIT; i < UDIM; i += 2) {
            const int n0i = (i + 2 < UDIM) ? (i + 2) : TSPLIT;  // wrap: harmless reload
            float4 N0 = __ldg(&g_Prec[n0i * UDIM + j]);
            float4 N1 = __ldg(&g_Prec[(n0i + 1) * UDIM + j]);

            #pragma unroll
            for (int k = 0; k < 2; k++) {
                const float4 p = (k == 0) ? P0 : P1;
                const float4* vp = reinterpret_cast<const float4*>(&vc[(i + k) * RPB]);
                float4 v0 = vp[0], v1 = vp[1];           // broadcast LDS.128
                float vv[RPB] = {v0.x, v0.y, v0.z, v0.w, v1.x, v1.y, v1.z, v1.w};
                #pragma unroll
                for (int r = 0; r < RPB; r++) {
                    float th = tanh_fast(fmaf(p.x, vv[r], p.y));
                    num[r] = fmaf(p.z, th, num[r]);
                    den[r] = fmaf(p.w, th, den[r]);
                }
            }
            P0 = N0; P1 = N1;
        }

        // old v (own slots) from current buffer
        float vold[RPB];
        {
            const float4* vo = reinterpret_cast<const float4*>(&vc[j * RPB]);
            float4 a = vo[0], b = vo[1];
            vold[0]=a.x; vold[1]=a.y; vold[2]=a.z; vold[3]=a.w;
            vold[4]=b.x; vold[5]=b.y; vold[6]=b.z; vold[7]=b.w;
        }

        float vn[RPB];
        #pragma unroll
        for (int r = 0; r < RPB; r++)
            vn[r] = __fdividef(fmaf(cmj, vold[r], gvj + num[r]), cgj + den[r]);

        float4* vw = reinterpret_cast<float4*>(&vT[nxt][j * RPB]);
        vw[0] = make_float4(vn[0], vn[1], vn[2], vn[3]);
        vw[1] = make_float4(vn[4], vn[5], vn[6], vn[7]);

        __syncthreads();
    }

    // ---- outputs: final state sits in vT[NUNFOLDS & 1] ----
    const float* vf = vT[NUNFOLDS & 1];
    if (out_v) {
        #pragma unroll
        for (int r = 0; r < RPB; r++)
            out_v[(row0 + r) * UDIM + j] = vf[j * RPB + r];
    }
    if (out_y && j == 0) {
        float ow = __ldg(&out_w[0]), ob = __ldg(&out_b[0]);
        #pragma unroll
        for (int r = 0; r < RPB; r++)
            out_y[row0 + r] = fmaf(vf[r], ow, ob);       // j == 0 -> slots 0..7
    }
}

extern "C" void kernel_launch(void* const* d_in, const int* in_sizes, int n_in,
                              void* d_out, int out_size)
{
    const float* inputs = (const float*)d_in[0];
    const float* state  = (const float*)d_in[1];
    const float* smu    = (const float*)d_in[2];
    const float* ssig   = (const float*)d_in[3];
    const float* sW     = (const float*)d_in[4];
    const float* serev  = (const float*)d_in[5];
    const float* mu     = (const float*)d_in[6];
    const float* sig    = (const float*)d_in[7];
    const float* W      = (const float*)d_in[8];
    const float* erev   = (const float*)d_in[9];
    const float* vleak  = (const float*)d_in[10];
    const float* gleak  = (const float*)d_in[11];
    const float* cm     = (const float*)d_in[12];
    const float* in_w   = (const float*)d_in[13];
    const float* in_b   = (const float*)d_in[14];
    const float* out_w  = (const float*)d_in[15];
    const float* out_b  = (const float*)d_in[16];

    const int batch = in_sizes[1] / UDIM;   // 8192

    float* out   = (float*)d_out;
    float* out_y = nullptr;
    float* out_v = nullptr;
    if (out_size == batch + batch * UDIM) {       // (outputs, v) concatenated
        out_y = out;
        out_v = out + batch;
    } else if (out_size == batch * UDIM) {        // v only
        out_v = out;
    } else {                                      // outputs only
        out_y = out;
    }

    prep_kernel<<<UDIM, UDIM + INDIM>>>(mu, sig, W, erev, smu, ssig, sW, serev);
    worm_kernel<<<batch / RPB, UDIM>>>(inputs, state, vleak, gleak, cm,
                                       in_w, in_b, out_w, out_b, out_y, out_v);
}